// round 3
// baseline (speedup 1.0000x reference)
#include <cuda_runtime.h>

#define SS   64
#define BB   32
#define HID  16
#define EMB  32
#define VV   50257
#define SB   (SS*BB)        // 2048
#define GG   64             // 4*HID gate outputs
#define COMB (EMB+HID)      // 48

// scratch (no allocations allowed)
__device__ float g_X[SB*GG];        // precomputed input-part of gates
__device__ float g_H[SB*2*HID];     // concat_h [sb][32]
__device__ float g_sumexp[SB];

// ---------------------------------------------------------------------------
// zero the sum-exp accumulator (graph-replay safe)
__global__ void k_zero() {
    int i = blockIdx.x * blockDim.x + threadIdx.x;
    if (i < SB) g_sumexp[i] = 0.f;
}

// ---------------------------------------------------------------------------
// K1: X[sb][g] = b_gate[h] + sum_e emb[idx[sb]][e] * W_gate[h][e]
__global__ void k_precompute(const int* __restrict__ idx,
                             const float* __restrict__ emb,
                             const float* __restrict__ Wf, const float* __restrict__ bf,
                             const float* __restrict__ Wi, const float* __restrict__ bi,
                             const float* __restrict__ Wc, const float* __restrict__ bc,
                             const float* __restrict__ Wo, const float* __restrict__ bo) {
    int t = blockIdx.x * blockDim.x + threadIdx.x;
    if (t >= SB * GG) return;
    int g    = t & 63;
    int sb   = t >> 6;
    int gate = g >> 4;
    int hh   = g & 15;
    const float* W  = gate == 0 ? Wf : gate == 1 ? Wi : gate == 2 ? Wc : Wo;
    const float* bb = gate == 0 ? bf : gate == 1 ? bi : gate == 2 ? bc : bo;
    const float* e  = emb + (long long)idx[sb] * EMB;
    const float* w  = W + hh * COMB;
    float acc = bb[hh];
#pragma unroll
    for (int k = 0; k < EMB; k++) acc = fmaf(e[k], w[k], acc);
    g_X[t] = acc;
}

// ---------------------------------------------------------------------------
// K2: bidirectional recurrence. One warp per (direction, batch) sequence.
// Thread t owns gate outputs g0=t (f|i) and g1=32+t (C~|o). h lives in lanes
// 0..15 and is broadcast via shfl. Stores the PRE-step hidden (lefts/rights).
__global__ void k_recur(const float* __restrict__ Wf, const float* __restrict__ Wi,
                        const float* __restrict__ Wc, const float* __restrict__ Wo,
                        const float* __restrict__ h0, const float* __restrict__ C0) {
    int b   = blockIdx.x & 31;
    int dir = blockIdx.x >> 5;
    int t   = threadIdx.x;          // 0..31
    int hh  = t & 15;
    const float* W0 = (t < 16) ? Wf : Wi;   // sigmoid gates
    const float* W1 = (t < 16) ? Wc : Wo;   // tanh (C~) / sigmoid (o)
    float w0[HID], w1[HID];
#pragma unroll
    for (int k = 0; k < HID; k++) {
        w0[k] = W0[hh * COMB + EMB + k];
        w1[k] = W1[hh * COMB + EMB + k];
    }
    float h = h0[hh];
    float C = C0[hh];
    for (int step = 0; step < SS; step++) {
        int s  = dir ? (SS - 1 - step) : step;
        int sb = s * BB + b;
        if (t < 16) g_H[sb * 32 + dir * 16 + t] = h;   // pre-step hidden
        float acc0 = g_X[sb * 64 + t];
        float acc1 = g_X[sb * 64 + 32 + t];
#pragma unroll
        for (int k = 0; k < HID; k++) {
            float hk = __shfl_sync(0xffffffffu, h, k);
            acc0 = fmaf(hk, w0[k], acc0);
            acc1 = fmaf(hk, w1[k], acc1);
        }
        float a0 = 1.f / (1.f + __expf(-acc0));                       // f or i
        float a1 = (t < 16) ? tanhf(acc1) : 1.f / (1.f + __expf(-acc1)); // C~ or o
        float iv = __shfl_down_sync(0xffffffffu, a0, 16);   // i[h] -> lane h
        float ov = __shfl_down_sync(0xffffffffu, a1, 16);   // o[h] -> lane h
        if (t < 16) {
            C = a0 * C + iv * a1;
            h = ov * tanhf(C);
        }
    }
}

// ---------------------------------------------------------------------------
// K3: 64v x 64sb tiled GEMM over K=32, smem staged k-major so the inner loop
// is 2x LDS.128 + 16 FFMA per k. phase 0: accumulate sum(exp(logit)) per sb.
// phase 1: recompute logits, write logit - log(sumexp).
#define VT 64
#define ST 64

__global__ __launch_bounds__(256)
void k_logits(const float* __restrict__ Who, const float* __restrict__ bho,
              float* __restrict__ out, int phase) {
    __shared__ float Ws[32][VT + 4];
    __shared__ float Hs[32][ST + 4];
    __shared__ float bs[VT];
    __shared__ float sume[ST];

    int tid    = threadIdx.x;
    int vbase  = blockIdx.x * VT;
    int sbbase = blockIdx.y * ST;

    {
        int r0 = tid >> 3;           // 0..31
        int k4 = (tid & 7) * 4;      // 0,4,...,28
#pragma unroll
        for (int r = 0; r < 2; r++) {
            int row = r * 32 + r0;
            int v = vbase + row;
            float4 w = (v < VV) ? *(const float4*)&Who[v * 32 + k4]
                                : make_float4(0.f, 0.f, 0.f, 0.f);
            Ws[k4 + 0][row] = w.x; Ws[k4 + 1][row] = w.y;
            Ws[k4 + 2][row] = w.z; Ws[k4 + 3][row] = w.w;
            int sb = sbbase + row;
            float4 hv = *(const float4*)&g_H[sb * 32 + k4];
            Hs[k4 + 0][row] = hv.x; Hs[k4 + 1][row] = hv.y;
            Hs[k4 + 2][row] = hv.z; Hs[k4 + 3][row] = hv.w;
        }
        if (tid < VT) bs[tid] = (vbase + tid < VV) ? bho[vbase + tid] : 0.f;
        if (tid < ST) sume[tid] = 0.f;
    }
    __syncthreads();

    int tx = tid & 15;    // v group (4 consecutive v)
    int ty = tid >> 4;    // sb group (4 consecutive sb)

    float acc[4][4];
#pragma unroll
    for (int i = 0; i < 4; i++) {
        float bv = bs[tx * 4 + i];
#pragma unroll
        for (int j = 0; j < 4; j++) acc[i][j] = bv;
    }

#pragma unroll
    for (int k = 0; k < 32; k++) {
        float4 w = *(const float4*)&Ws[k][tx * 4];
        float4 h = *(const float4*)&Hs[k][ty * 4];
        float wv[4] = {w.x, w.y, w.z, w.w};
        float hv[4] = {h.x, h.y, h.z, h.w};
#pragma unroll
        for (int i = 0; i < 4; i++)
#pragma unroll
            for (int j = 0; j < 4; j++)
                acc[i][j] = fmaf(wv[i], hv[j], acc[i][j]);
    }

    int v0 = vbase + tx * 4;
    if (phase == 0) {
        float part[4] = {0.f, 0.f, 0.f, 0.f};
#pragma unroll
        for (int i = 0; i < 4; i++) {
            if (v0 + i < VV) {
#pragma unroll
                for (int j = 0; j < 4; j++) part[j] += __expf(acc[i][j]);
            }
        }
#pragma unroll
        for (int j = 0; j < 4; j++) atomicAdd(&sume[ty * 4 + j], part[j]);
        __syncthreads();
        if (tid < ST) atomicAdd(&g_sumexp[sbbase + tid], sume[tid]);
    } else {
#pragma unroll
        for (int j = 0; j < 4; j++) {
            int sb = sbbase + ty * 4 + j;
            float lse = __logf(g_sumexp[sb]);
            int base = sb * VV + v0;
#pragma unroll
            for (int i = 0; i < 4; i++)
                if (v0 + i < VV) out[base + i] = acc[i][j] - lse;
        }
    }
}

// ---------------------------------------------------------------------------
extern "C" void kernel_launch(void* const* d_in, const int* in_sizes, int n_in,
                              void* d_out, int out_size) {
    const int*   idx = (const int*)  d_in[0];
    const float* emb = (const float*)d_in[1];
    const float* Wf  = (const float*)d_in[2];
    const float* bf  = (const float*)d_in[3];
    const float* Wi  = (const float*)d_in[4];
    const float* bi  = (const float*)d_in[5];
    const float* Wc  = (const float*)d_in[6];
    const float* bc  = (const float*)d_in[7];
    const float* Wo  = (const float*)d_in[8];
    const float* bo  = (const float*)d_in[9];
    const float* Who = (const float*)d_in[10];
    const float* bho = (const float*)d_in[11];
    const float* h0  = (const float*)d_in[12];
    const float* C0  = (const float*)d_in[13];
    float* out = (float*)d_out;

    k_precompute<<<(SB * GG + 255) / 256, 256>>>(idx, emb, Wf, bf, Wi, bi, Wc, bc, Wo, bo);
    k_recur<<<64, 32>>>(Wf, Wi, Wc, Wo, h0, C0);
    k_zero<<<(SB + 255) / 256, 256>>>();

    dim3 grid((VV + VT - 1) / VT, SB / ST);   // 786 x 32
    k_logits<<<grid, 256>>>(Who, bho, out, 0);
    k_logits<<<grid, 256>>>(Who, bho, out, 1);
}

// round 4
// speedup vs baseline: 1.4719x; 1.4719x over previous
#include <cuda_runtime.h>

#define SS   64
#define BB   32
#define HID  16
#define EMB  32
#define VV   50257
#define SB   (SS*BB)        // 2048
#define GG   64             // 4*HID gate outputs
#define COMB (EMB+HID)      // 48

// scratch (no allocations allowed)
__device__ float g_X[SB*GG];        // precomputed input-part of gates
__device__ float g_H[SB*2*HID];     // concat_h [sb][32]
__device__ float g_sumexp[SB];

using u64 = unsigned long long;

// packed f32x2 helpers (sm_100+ double-pumped fp32 path; only reachable via PTX)
__device__ __forceinline__ u64 fma2(u64 a, u64 b, u64 c) {
    u64 d; asm("fma.rn.f32x2 %0, %1, %2, %3;" : "=l"(d) : "l"(a), "l"(b), "l"(c));
    return d;
}
__device__ __forceinline__ u64 pack2(float x) {
    u64 d; asm("mov.b64 %0, {%1, %1};" : "=l"(d) : "f"(x));
    return d;
}
__device__ __forceinline__ float2 unpack2(u64 a) {
    float lo, hi; asm("mov.b64 {%0, %1}, %2;" : "=f"(lo), "=f"(hi) : "l"(a));
    return make_float2(lo, hi);
}

// ---------------------------------------------------------------------------
__global__ void k_zero() {
    int i = blockIdx.x * blockDim.x + threadIdx.x;
    if (i < SB) g_sumexp[i] = 0.f;
}

// ---------------------------------------------------------------------------
// K1: X[sb][g] = b_gate[h] + sum_e emb[idx[sb]][e] * W_gate[h][e]
__global__ void k_precompute(const int* __restrict__ idx,
                             const float* __restrict__ emb,
                             const float* __restrict__ Wf, const float* __restrict__ bf,
                             const float* __restrict__ Wi, const float* __restrict__ bi,
                             const float* __restrict__ Wc, const float* __restrict__ bc,
                             const float* __restrict__ Wo, const float* __restrict__ bo) {
    int t = blockIdx.x * blockDim.x + threadIdx.x;
    if (t >= SB * GG) return;
    int g    = t & 63;
    int sb   = t >> 6;
    int gate = g >> 4;
    int hh   = g & 15;
    const float* W  = gate == 0 ? Wf : gate == 1 ? Wi : gate == 2 ? Wc : Wo;
    const float* bb = gate == 0 ? bf : gate == 1 ? bi : gate == 2 ? bc : bo;
    const float* e  = emb + (long long)idx[sb] * EMB;
    const float* w  = W + hh * COMB;
    float acc = bb[hh];
#pragma unroll
    for (int k = 0; k < EMB; k++) acc = fmaf(e[k], w[k], acc);
    g_X[t] = acc;
}

// ---------------------------------------------------------------------------
// K2: bidirectional recurrence. One warp per (direction, batch) sequence.
__global__ void k_recur(const float* __restrict__ Wf, const float* __restrict__ Wi,
                        const float* __restrict__ Wc, const float* __restrict__ Wo,
                        const float* __restrict__ h0, const float* __restrict__ C0) {
    int b   = blockIdx.x & 31;
    int dir = blockIdx.x >> 5;
    int t   = threadIdx.x;          // 0..31
    int hh  = t & 15;
    const float* W0 = (t < 16) ? Wf : Wi;   // sigmoid gates
    const float* W1 = (t < 16) ? Wc : Wo;   // tanh (C~) / sigmoid (o)
    float w0[HID], w1[HID];
#pragma unroll
    for (int k = 0; k < HID; k++) {
        w0[k] = W0[hh * COMB + EMB + k];
        w1[k] = W1[hh * COMB + EMB + k];
    }
    float h = h0[hh];
    float C = C0[hh];
    for (int step = 0; step < SS; step++) {
        int s  = dir ? (SS - 1 - step) : step;
        int sb = s * BB + b;
        if (t < 16) g_H[sb * 32 + dir * 16 + t] = h;   // pre-step hidden
        float acc0 = g_X[sb * 64 + t];
        float acc1 = g_X[sb * 64 + 32 + t];
#pragma unroll
        for (int k = 0; k < HID; k++) {
            float hk = __shfl_sync(0xffffffffu, h, k);
            acc0 = fmaf(hk, w0[k], acc0);
            acc1 = fmaf(hk, w1[k], acc1);
        }
        float a0 = 1.f / (1.f + __expf(-acc0));                          // f or i
        float a1 = (t < 16) ? tanhf(acc1) : 1.f / (1.f + __expf(-acc1)); // C~ or o
        float iv = __shfl_down_sync(0xffffffffu, a0, 16);
        float ov = __shfl_down_sync(0xffffffffu, a1, 16);
        if (t < 16) {
            C = a0 * C + iv * a1;
            h = ov * tanhf(C);
        }
    }
}

// ---------------------------------------------------------------------------
// K3: 128v x 128sb tile, K=32 staged k-major in smem. 8x8 per-thread tile,
// accumulators packed 2-wide along sb via fma.rn.f32x2.
// Thread (tx,ty): v in {vbase + tx + 16*i}, sb in {sbbase + ty*4 + jj (jj<4),
// sbbase + 64 + ty*4 + (jj-4)} -> H pairs are consecutive floats (free packing),
// W is a lane-varying scalar duplicated into both halves.
// phase 0: accumulate sum(exp(logit)); phase 1: recompute, write logit - lse.
#define VT 128
#define ST 128

__global__ __launch_bounds__(256, 2)
void k_logits(const float* __restrict__ Who, const float* __restrict__ bho,
              float* __restrict__ out, int phase) {
    __shared__ float Ws[32][VT + 4];
    __shared__ float Hs[32][ST + 4];
    __shared__ float bs[VT];
    __shared__ float lss[ST];          // phase 1: per-sb log-sum-exp

    int tid    = threadIdx.x;
    int vbase  = blockIdx.x * VT;
    int sbbase = blockIdx.y * ST;

    // stage W (transposed k-major) and H
    for (int t = tid; t < VT * 8; t += 256) {
        int row = t >> 3;
        int kq  = (t & 7) * 4;
        int v = vbase + row;
        float4 w = (v < VV) ? *(const float4*)&Who[v * 32 + kq]
                            : make_float4(0.f, 0.f, 0.f, 0.f);
        Ws[kq + 0][row] = w.x; Ws[kq + 1][row] = w.y;
        Ws[kq + 2][row] = w.z; Ws[kq + 3][row] = w.w;
        float4 hv = *(const float4*)&g_H[(sbbase + row) * 32 + kq];
        Hs[kq + 0][row] = hv.x; Hs[kq + 1][row] = hv.y;
        Hs[kq + 2][row] = hv.z; Hs[kq + 3][row] = hv.w;
    }
    if (tid < VT) bs[tid] = (vbase + tid < VV) ? bho[vbase + tid] : 0.f;
    if (tid < ST) lss[tid] = phase ? __logf(g_sumexp[sbbase + tid]) : 0.f;
    __syncthreads();

    int tx = tid & 15;
    int ty = tid >> 4;

    u64 acc[8][4];                      // [v(i)][sb-pair(j2)]
#pragma unroll
    for (int i = 0; i < 8; i++) {
        u64 bv = pack2(bs[tx + 16 * i]);
#pragma unroll
        for (int j = 0; j < 4; j++) acc[i][j] = bv;
    }

#pragma unroll 4
    for (int k = 0; k < 32; k++) {
        ulonglong2 ha = *(const ulonglong2*)&Hs[k][ty * 4];
        ulonglong2 hb = *(const ulonglong2*)&Hs[k][64 + ty * 4];
        u64 h2[4] = {ha.x, ha.y, hb.x, hb.y};
#pragma unroll
        for (int i = 0; i < 8; i++) {
            u64 wp = pack2(Ws[k][tx + 16 * i]);
#pragma unroll
            for (int j = 0; j < 4; j++)
                acc[i][j] = fma2(wp, h2[j], acc[i][j]);
        }
    }

    if (phase == 0) {
        float part[8];
#pragma unroll
        for (int j = 0; j < 8; j++) part[j] = 0.f;
#pragma unroll
        for (int i = 0; i < 8; i++) {
            if (vbase + tx + 16 * i < VV) {
#pragma unroll
                for (int j = 0; j < 4; j++) {
                    float2 p = unpack2(acc[i][j]);
                    part[2 * j]     += __expf(p.x);
                    part[2 * j + 1] += __expf(p.y);
                }
            }
        }
        // reduce over the 16 lanes sharing the same ty (xor stays within halves)
#pragma unroll
        for (int j = 0; j < 8; j++) {
#pragma unroll
            for (int off = 1; off < 16; off <<= 1)
                part[j] += __shfl_xor_sync(0xffffffffu, part[j], off);
        }
        if (tx == 0) {
#pragma unroll
            for (int jj = 0; jj < 8; jj++) {
                int sbj = (jj < 4) ? ty * 4 + jj : 64 + ty * 4 + (jj - 4);
                atomicAdd(&g_sumexp[sbbase + sbj], part[jj]);
            }
        }
    } else {
#pragma unroll
        for (int jj = 0; jj < 8; jj++) {
            int sbj = (jj < 4) ? ty * 4 + jj : 64 + ty * 4 + (jj - 4);
            float lse = lss[sbj];
            int j2 = jj >> 1;
            int base = (sbbase + sbj) * VV + vbase;
#pragma unroll
            for (int i = 0; i < 8; i++) {
                int v = tx + 16 * i;
                if (vbase + v < VV) {
                    float2 p = unpack2(acc[i][j2]);
                    out[base + v] = ((jj & 1) ? p.y : p.x) - lse;
                }
            }
        }
    }
}

// ---------------------------------------------------------------------------
extern "C" void kernel_launch(void* const* d_in, const int* in_sizes, int n_in,
                              void* d_out, int out_size) {
    const int*   idx = (const int*)  d_in[0];
    const float* emb = (const float*)d_in[1];
    const float* Wf  = (const float*)d_in[2];
    const float* bf  = (const float*)d_in[3];
    const float* Wi  = (const float*)d_in[4];
    const float* bi  = (const float*)d_in[5];
    const float* Wc  = (const float*)d_in[6];
    const float* bc  = (const float*)d_in[7];
    const float* Wo  = (const float*)d_in[8];
    const float* bo  = (const float*)d_in[9];
    const float* Who = (const float*)d_in[10];
    const float* bho = (const float*)d_in[11];
    const float* h0  = (const float*)d_in[12];
    const float* C0  = (const float*)d_in[13];
    float* out = (float*)d_out;

    k_precompute<<<(SB * GG + 255) / 256, 256>>>(idx, emb, Wf, bf, Wi, bi, Wc, bc, Wo, bo);
    k_recur<<<64, 32>>>(Wf, Wi, Wc, Wo, h0, C0);
    k_zero<<<(SB + 255) / 256, 256>>>();

    dim3 grid((VV + VT - 1) / VT, SB / ST);   // 393 x 16
    k_logits<<<grid, 256>>>(Who, bho, out, 0);
    k_logits<<<grid, 256>>>(Who, bho, out, 1);
}